// round 1
// baseline (speedup 1.0000x reference)
#include <cuda_runtime.h>
#include <cstdint>

// Problem dims
#define BB 64
#define NN 512
#define DD 1024
#define ROWS (BB * NN)   // 32768

// Scratch (device globals — no runtime allocation allowed)
__device__ float g_DU[(size_t)ROWS * DD];   // 128 MiB: DU[:, :1024]
__device__ float g_U [(size_t)DD * DD];     // packed U[:, :1024], 16B-aligned rows
__device__ float g_bx[ROWS];                // DU[:,1024] + Ha·W_h
__device__ float g_by[ROWS];                // D·W_d

// ---------------------------------------------------------------------------
// Pack U[:, :1024] (stride 1025, misaligned) into an aligned 1024x1024 buffer
// ---------------------------------------------------------------------------
__global__ void pack_u_kernel(const float* __restrict__ U) {
    int idx = blockIdx.x * blockDim.x + threadIdx.x;   // 1M threads
    int r = idx >> 10;
    int c = idx & 1023;
    g_U[idx] = U[r * 1025 + c];
}

// ---------------------------------------------------------------------------
// Bias kernel: per row r = (b,n):
//   bx[r] = sum_i D[r,i]*U[i,1024] + sum_j H[r,j]*W[j] + W[1024]
//   by[r] = sum_i D[r,i]*W[1025+i]
// One warp per row; U column / W slices staged in shared memory per block.
// ---------------------------------------------------------------------------
__global__ __launch_bounds__(256)
void bias_kernel(const float* __restrict__ D, const float* __restrict__ H,
                 const float* __restrict__ U, const float* __restrict__ W) {
    __shared__ float sU[DD];
    __shared__ float sWh[DD];
    __shared__ float sWd[DD];

    for (int i = threadIdx.x; i < DD; i += blockDim.x) {
        sU[i]  = U[i * 1025 + 1024];
        sWh[i] = W[i];
        sWd[i] = W[1025 + i];
    }
    __syncthreads();

    int warp = (blockIdx.x * blockDim.x + threadIdx.x) >> 5;   // global row
    int lane = threadIdx.x & 31;
    if (warp >= ROWS) return;

    const float4* drow = (const float4*)(D + (size_t)warp * DD);
    const float4* hrow = (const float4*)(H + (size_t)warp * DD);

    float s1 = 0.f, s2 = 0.f, s3 = 0.f;
    #pragma unroll
    for (int it = 0; it < 8; it++) {
        int i4 = it * 32 + lane;
        float4 d = drow[i4];
        float4 h = hrow[i4];
        int i = i4 * 4;
        s1 += d.x * sU[i]   + d.y * sU[i+1]   + d.z * sU[i+2]   + d.w * sU[i+3];
        s2 += h.x * sWh[i]  + h.y * sWh[i+1]  + h.z * sWh[i+2]  + h.w * sWh[i+3];
        s3 += d.x * sWd[i]  + d.y * sWd[i+1]  + d.z * sWd[i+2]  + d.w * sWd[i+3];
    }
    #pragma unroll
    for (int o = 16; o > 0; o >>= 1) {
        s1 += __shfl_xor_sync(0xFFFFFFFFu, s1, o);
        s2 += __shfl_xor_sync(0xFFFFFFFFu, s2, o);
        s3 += __shfl_xor_sync(0xFFFFFFFFu, s3, o);
    }
    if (lane == 0) {
        g_bx[warp] = s1 + s2 + W[1024];
        g_by[warp] = s3;
    }
}

// ---------------------------------------------------------------------------
// GEMM A (NN): g_DU = D_flat(32768x1024) @ g_U(1024x1024)
// 128x128 tile, BK=8, 256 threads, 8x8 per thread (64-split fragment layout)
// ---------------------------------------------------------------------------
__global__ __launch_bounds__(256, 2)
void gemm_du_kernel(const float* __restrict__ A) {
    __shared__ float As[8][128];
    __shared__ float Bs[8][128];

    const int tid = threadIdx.x;
    const int tx = tid & 15;         // 16 col-threads
    const int ty = tid >> 4;         // 16 row-threads

    const float* Ap = A   + (size_t)blockIdx.y * 128 * DD;
    const float* Bp = g_U + (size_t)blockIdx.x * 128;

    const int arow = tid >> 1;
    const int ak4  = (tid & 1) * 4;
    const int brow = tid >> 5;
    const int bc4  = (tid & 31) * 4;

    float acc[8][8];
    #pragma unroll
    for (int i = 0; i < 8; i++)
        #pragma unroll
        for (int j = 0; j < 8; j++) acc[i][j] = 0.f;

    for (int k0 = 0; k0 < DD; k0 += 8) {
        float4 av = *(const float4*)(Ap + (size_t)arow * DD + k0 + ak4);
        float4 bv = *(const float4*)(Bp + (size_t)(k0 + brow) * DD + bc4);
        As[ak4 + 0][arow] = av.x;
        As[ak4 + 1][arow] = av.y;
        As[ak4 + 2][arow] = av.z;
        As[ak4 + 3][arow] = av.w;
        *(float4*)&Bs[brow][bc4] = bv;
        __syncthreads();

        #pragma unroll
        for (int k = 0; k < 8; k++) {
            float4 a0 = *(const float4*)&As[k][ty * 4];
            float4 a1 = *(const float4*)&As[k][64 + ty * 4];
            float4 b0 = *(const float4*)&Bs[k][tx * 4];
            float4 b1 = *(const float4*)&Bs[k][64 + tx * 4];
            float af[8] = {a0.x, a0.y, a0.z, a0.w, a1.x, a1.y, a1.z, a1.w};
            float bf[8] = {b0.x, b0.y, b0.z, b0.w, b1.x, b1.y, b1.z, b1.w};
            #pragma unroll
            for (int i = 0; i < 8; i++)
                #pragma unroll
                for (int j = 0; j < 8; j++)
                    acc[i][j] += af[i] * bf[j];
        }
        __syncthreads();
    }

    float* C = g_DU + (size_t)blockIdx.y * 128 * DD + (size_t)blockIdx.x * 128;
    #pragma unroll
    for (int ii = 0; ii < 2; ii++) {
        #pragma unroll
        for (int i = 0; i < 4; i++) {
            int row = ii * 64 + ty * 4 + i;
            #pragma unroll
            for (int jj = 0; jj < 2; jj++) {
                float4 v = make_float4(acc[ii*4+i][jj*4+0], acc[ii*4+i][jj*4+1],
                                       acc[ii*4+i][jj*4+2], acc[ii*4+i][jj*4+3]);
                *(float4*)&C[(size_t)row * DD + jj * 64 + tx * 4] = v;
            }
        }
    }
}

// ---------------------------------------------------------------------------
// GEMM B (NT, batched): out[b] = g_DU[b](512x1024) @ H[b](512x1024)^T + bx + by
// Same tiling; both operands K-contiguous.
// ---------------------------------------------------------------------------
__global__ __launch_bounds__(256, 2)
void gemm_out_kernel(const float* __restrict__ H, float* __restrict__ out) {
    __shared__ float As[8][128];
    __shared__ float Bs[8][128];

    const int tid = threadIdx.x;
    const int tx = tid & 15;
    const int ty = tid >> 4;
    const int b  = blockIdx.z;

    const float* Ap = g_DU + ((size_t)b * NN + blockIdx.y * 128) * DD;
    const float* Bp = H    + ((size_t)b * NN + blockIdx.x * 128) * DD;

    const int r  = tid >> 1;
    const int k4 = (tid & 1) * 4;

    float acc[8][8];
    #pragma unroll
    for (int i = 0; i < 8; i++)
        #pragma unroll
        for (int j = 0; j < 8; j++) acc[i][j] = 0.f;

    for (int k0 = 0; k0 < DD; k0 += 8) {
        float4 av = *(const float4*)(Ap + (size_t)r * DD + k0 + k4);
        float4 bv = *(const float4*)(Bp + (size_t)r * DD + k0 + k4);
        As[k4 + 0][r] = av.x;
        As[k4 + 1][r] = av.y;
        As[k4 + 2][r] = av.z;
        As[k4 + 3][r] = av.w;
        Bs[k4 + 0][r] = bv.x;
        Bs[k4 + 1][r] = bv.y;
        Bs[k4 + 2][r] = bv.z;
        Bs[k4 + 3][r] = bv.w;
        __syncthreads();

        #pragma unroll
        for (int k = 0; k < 8; k++) {
            float4 a0 = *(const float4*)&As[k][ty * 4];
            float4 a1 = *(const float4*)&As[k][64 + ty * 4];
            float4 b0 = *(const float4*)&Bs[k][tx * 4];
            float4 b1 = *(const float4*)&Bs[k][64 + tx * 4];
            float af[8] = {a0.x, a0.y, a0.z, a0.w, a1.x, a1.y, a1.z, a1.w};
            float bf[8] = {b0.x, b0.y, b0.z, b0.w, b1.x, b1.y, b1.z, b1.w};
            #pragma unroll
            for (int i = 0; i < 8; i++)
                #pragma unroll
                for (int j = 0; j < 8; j++)
                    acc[i][j] += af[i] * bf[j];
        }
        __syncthreads();
    }

    #pragma unroll
    for (int ii = 0; ii < 2; ii++) {
        #pragma unroll
        for (int i = 0; i < 4; i++) {
            int rg = blockIdx.y * 128 + ii * 64 + ty * 4 + i;
            float bxv = g_bx[b * NN + rg];
            float* orow = out + ((size_t)b * NN + rg) * NN + blockIdx.x * 128;
            #pragma unroll
            for (int jj = 0; jj < 2; jj++) {
                int cb = jj * 64 + tx * 4;
                float4 byv = *(const float4*)&g_by[b * NN + blockIdx.x * 128 + cb];
                float4 v;
                v.x = acc[ii*4+i][jj*4+0] + bxv + byv.x;
                v.y = acc[ii*4+i][jj*4+1] + bxv + byv.y;
                v.z = acc[ii*4+i][jj*4+2] + bxv + byv.z;
                v.w = acc[ii*4+i][jj*4+3] + bxv + byv.w;
                *(float4*)&orow[cb] = v;
            }
        }
    }
}

// ---------------------------------------------------------------------------
// Launch
// ---------------------------------------------------------------------------
extern "C" void kernel_launch(void* const* d_in, const int* in_sizes, int n_in,
                              void* d_out, int out_size) {
    const float* D = (const float*)d_in[0];
    const float* H = (const float*)d_in[1];
    const float* U = (const float*)d_in[2];
    const float* W = (const float*)d_in[3];
    float* out = (float*)d_out;

    pack_u_kernel<<<(DD * DD) / 256, 256>>>(U);
    bias_kernel<<<(ROWS * 32) / 256, 256>>>(D, H, U, W);

    dim3 gridA(DD / 128, ROWS / 128);          // (8, 256)
    gemm_du_kernel<<<gridA, 256>>>(D);

    dim3 gridB(NN / 128, NN / 128, BB);        // (4, 4, 64)
    gemm_out_kernel<<<gridB, 256>>>(H, out);
}

// round 3
// speedup vs baseline: 2.7049x; 2.7049x over previous
#include <cuda_runtime.h>
#include <cuda_bf16.h>
#include <cstdint>

#define BB 64
#define NN 512
#define DD 1024
#define ROWS (BB * NN)   // 32768

// ---------------------------------------------------------------------------
// Device scratch (no runtime allocation allowed)
// ---------------------------------------------------------------------------
__device__ __nv_bfloat16 g_Dhi[(size_t)ROWS * DD];
__device__ __nv_bfloat16 g_Dlo[(size_t)ROWS * DD];
__device__ __nv_bfloat16 g_Hhi[(size_t)ROWS * DD];
__device__ __nv_bfloat16 g_Hlo[(size_t)ROWS * DD];
__device__ __nv_bfloat16 g_DUhi[(size_t)ROWS * DD];
__device__ __nv_bfloat16 g_DUlo[(size_t)ROWS * DD];
__device__ __nv_bfloat16 g_Uthi[(size_t)DD * DD];   // U^T (N-major rows, K contiguous)
__device__ __nv_bfloat16 g_Utlo[(size_t)DD * DD];
__device__ float g_bx[ROWS];
__device__ float g_by[ROWS];

// ---------------------------------------------------------------------------
// Helpers
// ---------------------------------------------------------------------------
__device__ __forceinline__ uint32_t smem_u32(const void* p) {
    uint32_t a;
    asm("{ .reg .u64 t; cvta.to.shared.u64 t, %1; cvt.u32.u64 %0, t; }" : "=r"(a) : "l"(p));
    return a;
}

__device__ __forceinline__ void cp_async16(uint32_t dst, const void* src) {
    asm volatile("cp.async.cg.shared.global [%0], [%1], 16;" :: "r"(dst), "l"(src));
}

#define CP_COMMIT() asm volatile("cp.async.commit_group;")

__device__ __forceinline__ void split_pack(float a, float b, unsigned& hi, unsigned& lo) {
    __nv_bfloat16 ha = __float2bfloat16(a);
    __nv_bfloat16 hb = __float2bfloat16(b);
    __nv_bfloat16 la = __float2bfloat16(a - __bfloat162float(ha));
    __nv_bfloat16 lb = __float2bfloat16(b - __bfloat162float(hb));
    hi = (unsigned)__bfloat16_as_ushort(ha) | ((unsigned)__bfloat16_as_ushort(hb) << 16);
    lo = (unsigned)__bfloat16_as_ushort(la) | ((unsigned)__bfloat16_as_ushort(lb) << 16);
}

// Swizzled smem address: off = row*128 + col16*16, XOR bits[6:4] with row&7
__device__ __forceinline__ uint32_t sw_addr(uint32_t base, int row, int col16) {
    uint32_t off = (uint32_t)(row * 128 + col16 * 16);
    return base + (off ^ (((uint32_t)row & 7u) << 4));
}

#define LDSM4(r0, r1, r2, r3, addr) \
    asm volatile("ldmatrix.sync.aligned.m8n8.x4.shared.b16 {%0,%1,%2,%3}, [%4];" \
                 : "=r"(r0), "=r"(r1), "=r"(r2), "=r"(r3) : "r"(addr))

#define MMA16816(c, a0, a1, a2, a3, b0, b1) \
    asm volatile("mma.sync.aligned.m16n8k16.row.col.f32.bf16.bf16.f32 " \
                 "{%0,%1,%2,%3}, {%4,%5,%6,%7}, {%8,%9}, {%0,%1,%2,%3};" \
                 : "+f"((c)[0]), "+f"((c)[1]), "+f"((c)[2]), "+f"((c)[3]) \
                 : "r"(a0), "r"(a1), "r"(a2), "r"(a3), "r"(b0), "r"(b1))

// ---------------------------------------------------------------------------
// Prep: split D,H into bf16 hi/lo + bias reductions (fused, one warp per row)
// ---------------------------------------------------------------------------
__global__ __launch_bounds__(256)
void prep_split_bias(const float* __restrict__ D, const float* __restrict__ H,
                     const float* __restrict__ U, const float* __restrict__ W) {
    __shared__ float sU[DD], sWh[DD], sWd[DD];
    for (int i = threadIdx.x; i < DD; i += blockDim.x) {
        sU[i]  = U[i * 1025 + 1024];
        sWh[i] = W[i];
        sWd[i] = W[1025 + i];
    }
    __syncthreads();

    int row  = (blockIdx.x * blockDim.x + threadIdx.x) >> 5;
    int lane = threadIdx.x & 31;
    if (row >= ROWS) return;

    const float4* drow = (const float4*)(D + (size_t)row * DD);
    const float4* hrow = (const float4*)(H + (size_t)row * DD);
    uint2* dh = (uint2*)(g_Dhi + (size_t)row * DD);
    uint2* dl = (uint2*)(g_Dlo + (size_t)row * DD);
    uint2* hh = (uint2*)(g_Hhi + (size_t)row * DD);
    uint2* hl = (uint2*)(g_Hlo + (size_t)row * DD);

    float s1 = 0.f, s2 = 0.f, s3 = 0.f;
    #pragma unroll
    for (int it = 0; it < 8; it++) {
        int i4 = it * 32 + lane;
        float4 d = drow[i4];
        float4 h = hrow[i4];
        int i = i4 * 4;
        s1 += d.x * sU[i]  + d.y * sU[i+1]  + d.z * sU[i+2]  + d.w * sU[i+3];
        s2 += h.x * sWh[i] + h.y * sWh[i+1] + h.z * sWh[i+2] + h.w * sWh[i+3];
        s3 += d.x * sWd[i] + d.y * sWd[i+1] + d.z * sWd[i+2] + d.w * sWd[i+3];

        unsigned a0, a1, b0, b1;
        split_pack(d.x, d.y, a0, b0);
        split_pack(d.z, d.w, a1, b1);
        dh[i4] = make_uint2(a0, a1);
        dl[i4] = make_uint2(b0, b1);
        split_pack(h.x, h.y, a0, b0);
        split_pack(h.z, h.w, a1, b1);
        hh[i4] = make_uint2(a0, a1);
        hl[i4] = make_uint2(b0, b1);
    }
    #pragma unroll
    for (int o = 16; o > 0; o >>= 1) {
        s1 += __shfl_xor_sync(0xFFFFFFFFu, s1, o);
        s2 += __shfl_xor_sync(0xFFFFFFFFu, s2, o);
        s3 += __shfl_xor_sync(0xFFFFFFFFu, s3, o);
    }
    if (lane == 0) {
        g_bx[row] = s1 + s2 + W[1024];
        g_by[row] = s3;
    }
}

// ---------------------------------------------------------------------------
// Prep: U^T split (read U[k][n] stride 1025, write Ut[n][k] hi/lo bf16)
// ---------------------------------------------------------------------------
__global__ void prep_u(const float* __restrict__ U) {
    __shared__ float t[32][33];
    int k0 = blockIdx.x * 32, n0 = blockIdx.y * 32;
    for (int i = threadIdx.y; i < 32; i += 8)
        t[i][threadIdx.x] = U[(size_t)(k0 + i) * 1025 + n0 + threadIdx.x];
    __syncthreads();
    for (int i = threadIdx.y; i < 32; i += 8) {
        float v = t[threadIdx.x][i];
        size_t o = (size_t)(n0 + i) * DD + k0 + threadIdx.x;
        __nv_bfloat16 h = __float2bfloat16(v);
        g_Uthi[o] = h;
        g_Utlo[o] = __float2bfloat16(v - __bfloat162float(h));
    }
}

// ---------------------------------------------------------------------------
// GEMM core: C(128x128 fp32 in regs) = Ahi*Bhi + Ahi*Blo + Alo*Bhi
// A, B: 128 rows x 1024 cols bf16, K-major. 3-stage cp.async, BK=64.
// 256 threads, 8 warps (4x2), warp tile 32x64, mma.sync m16n8k16.
// ---------------------------------------------------------------------------
#define STAGE_BYTES 32768
#define SMEM_TOTAL  (3 * STAGE_BYTES)

__device__ __forceinline__ void load_chunk(uint32_t tile,
        const __nv_bfloat16* Asrc, const __nv_bfloat16* Bsrc, int tid) {
    #pragma unroll
    for (int i = 0; i < 4; i++) {
        int idx = i * 256 + tid;
        int row = idx >> 3, g = idx & 7;
        uint32_t off = (uint32_t)(row * 128 + g * 16);
        uint32_t so = off ^ ((off >> 3) & 0x70);
        cp_async16(tile + so,         (const char*)Asrc + (size_t)row * 2048 + g * 16);
        cp_async16(tile + 16384 + so, (const char*)Bsrc + (size_t)row * 2048 + g * 16);
    }
}

__device__ __forceinline__ void gemm_core(uint32_t sb,
        const __nv_bfloat16* Ahi, const __nv_bfloat16* Alo,
        const __nv_bfloat16* Bhi, const __nv_bfloat16* Blo,
        float acc[2][8][4]) {
    const int tid  = threadIdx.x;
    const int lane = tid & 31;
    const int warp = tid >> 5;
    const int wm = warp >> 1;          // 0..3
    const int wn = warp & 1;           // 0..1

    #pragma unroll
    for (int mt = 0; mt < 2; mt++)
        #pragma unroll
        for (int n8 = 0; n8 < 8; n8++)
            #pragma unroll
            for (int q = 0; q < 4; q++) acc[mt][n8][q] = 0.f;

    // Prologue: 3 chunks of pass 0
    #pragma unroll
    for (int c = 0; c < 3; c++) {
        load_chunk(sb + c * STAGE_BYTES, Ahi + c * 64, Bhi + c * 64, tid);
        CP_COMMIT();
    }

    // Per-lane ldmatrix row/col components
    const int a_row = lane & 15;               // + wm*32 + mt*16
    const int a_kc  = lane >> 4;               // 16B chunk within k16
    const int b_row = (lane & 7) + ((lane >> 4) & 1) * 8;  // + wn*64 + nt*16
    const int b_kc  = (lane >> 3) & 1;

    #pragma unroll 1
    for (int c = 0; c < 48; c++) {
        const int s = c % 3;
        const uint32_t tile = sb + s * STAGE_BYTES;

        if (c < 46)       asm volatile("cp.async.wait_group 2;");
        else if (c == 46) asm volatile("cp.async.wait_group 1;");
        else              asm volatile("cp.async.wait_group 0;");
        __syncthreads();

        #pragma unroll
        for (int ks = 0; ks < 4; ks++) {
            uint32_t a[2][4], b[4][4];
            #pragma unroll
            for (int mt = 0; mt < 2; mt++) {
                uint32_t ad = sw_addr(tile, wm * 32 + mt * 16 + a_row, ks * 2 + a_kc);
                LDSM4(a[mt][0], a[mt][1], a[mt][2], a[mt][3], ad);
            }
            #pragma unroll
            for (int nt = 0; nt < 4; nt++) {
                uint32_t bd = sw_addr(tile + 16384, wn * 64 + nt * 16 + b_row, ks * 2 + b_kc);
                LDSM4(b[nt][0], b[nt][1], b[nt][2], b[nt][3], bd);
            }
            #pragma unroll
            for (int mt = 0; mt < 2; mt++)
                #pragma unroll
                for (int n8 = 0; n8 < 8; n8++) {
                    const int nt = n8 >> 1, h = (n8 & 1) * 2;
                    MMA16816(acc[mt][n8], a[mt][0], a[mt][1], a[mt][2], a[mt][3],
                             b[nt][h], b[nt][h + 1]);
                }
        }
        __syncthreads();

        if (c + 3 < 48) {
            const int cn = c + 3;
            const int pass = cn >> 4, kc = cn & 15;
            const __nv_bfloat16* As = (pass == 2) ? Alo : Ahi;
            const __nv_bfloat16* Bs = (pass == 1) ? Blo : Bhi;
            load_chunk(tile, As + kc * 64, Bs + kc * 64, tid);
            CP_COMMIT();
        }
    }
}

// ---------------------------------------------------------------------------
// GEMM A: DU = D @ U^T'  -> split result to bf16 hi/lo.  grid (8, 256)
// ---------------------------------------------------------------------------
__global__ __launch_bounds__(256, 2)
void gemm_du_tc() {
    extern __shared__ char smem[];
    uint32_t sb = smem_u32(smem);

    const __nv_bfloat16* Ahi = g_Dhi  + (size_t)blockIdx.y * 128 * DD;
    const __nv_bfloat16* Alo = g_Dlo  + (size_t)blockIdx.y * 128 * DD;
    const __nv_bfloat16* Bhi = g_Uthi + (size_t)blockIdx.x * 128 * DD;
    const __nv_bfloat16* Blo = g_Utlo + (size_t)blockIdx.x * 128 * DD;

    float acc[2][8][4];
    gemm_core(sb, Ahi, Alo, Bhi, Blo, acc);

    const int lane = threadIdx.x & 31;
    const int warp = threadIdx.x >> 5;
    const int wm = warp >> 1, wn = warp & 1;
    const int gid = lane >> 2, tig = lane & 3;

    #pragma unroll
    for (int mt = 0; mt < 2; mt++) {
        #pragma unroll
        for (int h = 0; h < 2; h++) {
            const int row = blockIdx.y * 128 + wm * 32 + mt * 16 + gid + h * 8;
            #pragma unroll
            for (int n8 = 0; n8 < 8; n8++) {
                const int col = blockIdx.x * 128 + wn * 64 + n8 * 8 + tig * 2;
                unsigned hi, lo;
                split_pack(acc[mt][n8][h * 2], acc[mt][n8][h * 2 + 1], hi, lo);
                *(unsigned*)(g_DUhi + (size_t)row * DD + col) = hi;
                *(unsigned*)(g_DUlo + (size_t)row * DD + col) = lo;
            }
        }
    }
}

// ---------------------------------------------------------------------------
// GEMM B: out[b] = DU[b] @ H[b]^T + bx + by.  grid (4, 4, 64)
// ---------------------------------------------------------------------------
__global__ __launch_bounds__(256, 2)
void gemm_out_tc(float* __restrict__ out) {
    extern __shared__ char smem[];
    uint32_t sb = smem_u32(smem);
    const int b = blockIdx.z;

    const size_t arow = (size_t)b * NN + blockIdx.y * 128;
    const size_t brow = (size_t)b * NN + blockIdx.x * 128;
    const __nv_bfloat16* Ahi = g_DUhi + arow * DD;
    const __nv_bfloat16* Alo = g_DUlo + arow * DD;
    const __nv_bfloat16* Bhi = g_Hhi  + brow * DD;
    const __nv_bfloat16* Blo = g_Hlo  + brow * DD;

    float acc[2][8][4];
    gemm_core(sb, Ahi, Alo, Bhi, Blo, acc);

    const int lane = threadIdx.x & 31;
    const int warp = threadIdx.x >> 5;
    const int wm = warp >> 1, wn = warp & 1;
    const int gid = lane >> 2, tig = lane & 3;

    #pragma unroll
    for (int mt = 0; mt < 2; mt++) {
        #pragma unroll
        for (int h = 0; h < 2; h++) {
            const int xg = blockIdx.y * 128 + wm * 32 + mt * 16 + gid + h * 8;
            const float bxv = g_bx[b * NN + xg];
            float* orow = out + ((size_t)b * NN + xg) * NN;
            #pragma unroll
            for (int n8 = 0; n8 < 8; n8++) {
                const int col = blockIdx.x * 128 + wn * 64 + n8 * 8 + tig * 2;
                float2 byv = *(const float2*)(g_by + b * NN + col);
                float2 v;
                v.x = acc[mt][n8][h * 2]     + bxv + byv.x;
                v.y = acc[mt][n8][h * 2 + 1] + bxv + byv.y;
                *(float2*)(orow + col) = v;
            }
        }
    }
}

// ---------------------------------------------------------------------------
// Launch
// ---------------------------------------------------------------------------
extern "C" void kernel_launch(void* const* d_in, const int* in_sizes, int n_in,
                              void* d_out, int out_size) {
    const float* D = (const float*)d_in[0];
    const float* H = (const float*)d_in[1];
    const float* U = (const float*)d_in[2];
    const float* W = (const float*)d_in[3];
    float* out = (float*)d_out;

    cudaFuncSetAttribute(gemm_du_tc,  cudaFuncAttributeMaxDynamicSharedMemorySize, SMEM_TOTAL);
    cudaFuncSetAttribute(gemm_out_tc, cudaFuncAttributeMaxDynamicSharedMemorySize, SMEM_TOTAL);

    prep_split_bias<<<(ROWS * 32) / 256, 256>>>(D, H, U, W);
    prep_u<<<dim3(32, 32), dim3(32, 8)>>>(U);

    gemm_du_tc<<<dim3(8, 256), 256, SMEM_TOTAL>>>();
    gemm_out_tc<<<dim3(4, 4, 64), 256, SMEM_TOTAL>>>(out);
}

// round 4
// speedup vs baseline: 6.8681x; 2.5391x over previous
#include <cuda_runtime.h>
#include <cuda_fp16.h>
#include <cstdint>

#define BB 64
#define NN 512
#define DD 1024
#define ROWS (BB * NN)   // 32768

// ---------------------------------------------------------------------------
// Device scratch (no runtime allocation allowed)
// ---------------------------------------------------------------------------
__device__ __half g_Dh [(size_t)ROWS * DD];
__device__ __half g_Hh [(size_t)ROWS * DD];
__device__ __half g_DUh[(size_t)ROWS * DD];
__device__ __half g_Ut [(size_t)DD * DD];    // U^T (N-major rows, K contiguous)
__device__ float g_bx[ROWS];
__device__ float g_by[ROWS];

// ---------------------------------------------------------------------------
// Helpers
// ---------------------------------------------------------------------------
__device__ __forceinline__ uint32_t smem_u32(const void* p) {
    uint32_t a;
    asm("{ .reg .u64 t; cvta.to.shared.u64 t, %1; cvt.u32.u64 %0, t; }" : "=r"(a) : "l"(p));
    return a;
}

__device__ __forceinline__ void cp_async16(uint32_t dst, const void* src) {
    asm volatile("cp.async.cg.shared.global [%0], [%1], 16;" :: "r"(dst), "l"(src));
}

#define CP_COMMIT() asm volatile("cp.async.commit_group;")

// Swizzled smem address: off = row*128 + col16*16, XOR bits[6:4] with row&7
__device__ __forceinline__ uint32_t sw_addr(uint32_t base, int row, int col16) {
    uint32_t off = (uint32_t)(row * 128 + col16 * 16);
    return base + (off ^ (((uint32_t)row & 7u) << 4));
}

#define LDSM4(r0, r1, r2, r3, addr) \
    asm volatile("ldmatrix.sync.aligned.m8n8.x4.shared.b16 {%0,%1,%2,%3}, [%4];" \
                 : "=r"(r0), "=r"(r1), "=r"(r2), "=r"(r3) : "r"(addr))

#define MMA16816(c, a0, a1, a2, a3, b0, b1) \
    asm volatile("mma.sync.aligned.m16n8k16.row.col.f32.f16.f16.f32 " \
                 "{%0,%1,%2,%3}, {%4,%5,%6,%7}, {%8,%9}, {%0,%1,%2,%3};" \
                 : "+f"((c)[0]), "+f"((c)[1]), "+f"((c)[2]), "+f"((c)[3]) \
                 : "r"(a0), "r"(a1), "r"(a2), "r"(a3), "r"(b0), "r"(b1))

// ---------------------------------------------------------------------------
// Prep: D,H -> fp16 + bias reductions (fused, one warp per row)
// ---------------------------------------------------------------------------
__global__ __launch_bounds__(256)
void prep_split_bias(const float* __restrict__ D, const float* __restrict__ H,
                     const float* __restrict__ U, const float* __restrict__ W) {
    __shared__ float sU[DD], sWh[DD], sWd[DD];
    for (int i = threadIdx.x; i < DD; i += blockDim.x) {
        sU[i]  = U[i * 1025 + 1024];
        sWh[i] = W[i];
        sWd[i] = W[1025 + i];
    }
    __syncthreads();

    int row  = (blockIdx.x * blockDim.x + threadIdx.x) >> 5;
    int lane = threadIdx.x & 31;
    if (row >= ROWS) return;

    const float4* drow = (const float4*)(D + (size_t)row * DD);
    const float4* hrow = (const float4*)(H + (size_t)row * DD);
    uint2* dh = (uint2*)(g_Dh + (size_t)row * DD);
    uint2* hh = (uint2*)(g_Hh + (size_t)row * DD);

    float s1 = 0.f, s2 = 0.f, s3 = 0.f;
    #pragma unroll
    for (int it = 0; it < 8; it++) {
        int i4 = it * 32 + lane;
        float4 d = drow[i4];
        float4 h = hrow[i4];
        int i = i4 * 4;
        s1 += d.x * sU[i]  + d.y * sU[i+1]  + d.z * sU[i+2]  + d.w * sU[i+3];
        s2 += h.x * sWh[i] + h.y * sWh[i+1] + h.z * sWh[i+2] + h.w * sWh[i+3];
        s3 += d.x * sWd[i] + d.y * sWd[i+1] + d.z * sWd[i+2] + d.w * sWd[i+3];

        __half2 d01 = __floats2half2_rn(d.x, d.y);
        __half2 d23 = __floats2half2_rn(d.z, d.w);
        __half2 h01 = __floats2half2_rn(h.x, h.y);
        __half2 h23 = __floats2half2_rn(h.z, h.w);
        dh[i4] = make_uint2(*(unsigned*)&d01, *(unsigned*)&d23);
        hh[i4] = make_uint2(*(unsigned*)&h01, *(unsigned*)&h23);
    }
    #pragma unroll
    for (int o = 16; o > 0; o >>= 1) {
        s1 += __shfl_xor_sync(0xFFFFFFFFu, s1, o);
        s2 += __shfl_xor_sync(0xFFFFFFFFu, s2, o);
        s3 += __shfl_xor_sync(0xFFFFFFFFu, s3, o);
    }
    if (lane == 0) {
        g_bx[row] = s1 + s2 + W[1024];
        g_by[row] = s3;
    }
}

// ---------------------------------------------------------------------------
// Prep: U^T -> fp16 (read U[k][n] stride 1025, write Ut[n][k])
// ---------------------------------------------------------------------------
__global__ void prep_u(const float* __restrict__ U) {
    __shared__ float t[32][33];
    int k0 = blockIdx.x * 32, n0 = blockIdx.y * 32;
    for (int i = threadIdx.y; i < 32; i += 8)
        t[i][threadIdx.x] = U[(size_t)(k0 + i) * 1025 + n0 + threadIdx.x];
    __syncthreads();
    for (int i = threadIdx.y; i < 32; i += 8) {
        float v = t[threadIdx.x][i];
        g_Ut[(size_t)(n0 + i) * DD + k0 + threadIdx.x] = __float2half_rn(v);
    }
}

// ---------------------------------------------------------------------------
// GEMM core: C(128x128 fp32 in regs) = A @ B^T, fp16 single pass.
// A, B: 128 rows x 1024 cols fp16, K-major. 3-stage cp.async, BK=64 (16 chunks).
// 256 threads, 8 warps (4x2), warp tile 32x64, mma.sync m16n8k16.
// ---------------------------------------------------------------------------
#define STAGE_BYTES 32768
#define SMEM_TOTAL  (3 * STAGE_BYTES)
#define NCHUNK 16

__device__ __forceinline__ void load_chunk(uint32_t tile,
        const __half* Asrc, const __half* Bsrc, int tid) {
    #pragma unroll
    for (int i = 0; i < 4; i++) {
        int idx = i * 256 + tid;
        int row = idx >> 3, g = idx & 7;
        uint32_t off = (uint32_t)(row * 128 + g * 16);
        uint32_t so = off ^ ((off >> 3) & 0x70);
        cp_async16(tile + so,         (const char*)Asrc + (size_t)row * 2048 + g * 16);
        cp_async16(tile + 16384 + so, (const char*)Bsrc + (size_t)row * 2048 + g * 16);
    }
}

__device__ __forceinline__ void gemm_core(uint32_t sb,
        const __half* A, const __half* B, float acc[2][8][4]) {
    const int tid  = threadIdx.x;
    const int lane = tid & 31;
    const int warp = tid >> 5;
    const int wm = warp >> 1;          // 0..3
    const int wn = warp & 1;           // 0..1

    #pragma unroll
    for (int mt = 0; mt < 2; mt++)
        #pragma unroll
        for (int n8 = 0; n8 < 8; n8++)
            #pragma unroll
            for (int q = 0; q < 4; q++) acc[mt][n8][q] = 0.f;

    // Prologue: 3 chunks
    #pragma unroll
    for (int c = 0; c < 3; c++) {
        load_chunk(sb + c * STAGE_BYTES, A + c * 64, B + c * 64, tid);
        CP_COMMIT();
    }

    const int a_row = lane & 15;
    const int a_kc  = lane >> 4;
    const int b_row = (lane & 7) + ((lane >> 4) & 1) * 8;
    const int b_kc  = (lane >> 3) & 1;

    #pragma unroll 1
    for (int c = 0; c < NCHUNK; c++) {
        const int s = c % 3;
        const uint32_t tile = sb + s * STAGE_BYTES;

        if (c < NCHUNK - 2)       asm volatile("cp.async.wait_group 2;");
        else if (c == NCHUNK - 2) asm volatile("cp.async.wait_group 1;");
        else                      asm volatile("cp.async.wait_group 0;");
        __syncthreads();

        #pragma unroll
        for (int ks = 0; ks < 4; ks++) {
            uint32_t a[2][4], b[4][4];
            #pragma unroll
            for (int mt = 0; mt < 2; mt++) {
                uint32_t ad = sw_addr(tile, wm * 32 + mt * 16 + a_row, ks * 2 + a_kc);
                LDSM4(a[mt][0], a[mt][1], a[mt][2], a[mt][3], ad);
            }
            #pragma unroll
            for (int nt = 0; nt < 4; nt++) {
                uint32_t bd = sw_addr(tile + 16384, wn * 64 + nt * 16 + b_row, ks * 2 + b_kc);
                LDSM4(b[nt][0], b[nt][1], b[nt][2], b[nt][3], bd);
            }
            #pragma unroll
            for (int mt = 0; mt < 2; mt++)
                #pragma unroll
                for (int n8 = 0; n8 < 8; n8++) {
                    const int nt = n8 >> 1, h = (n8 & 1) * 2;
                    MMA16816(acc[mt][n8], a[mt][0], a[mt][1], a[mt][2], a[mt][3],
                             b[nt][h], b[nt][h + 1]);
                }
        }
        __syncthreads();

        if (c + 3 < NCHUNK) {
            load_chunk(tile, A + (c + 3) * 64, B + (c + 3) * 64, tid);
            CP_COMMIT();
        }
    }
}

// ---------------------------------------------------------------------------
// GEMM A: DU = D @ U^T' -> fp16.  grid (8, 256)
// ---------------------------------------------------------------------------
__global__ __launch_bounds__(256, 2)
void gemm_du_tc() {
    extern __shared__ char smem[];
    uint32_t sb = smem_u32(smem);

    const __half* A = g_Dh + (size_t)blockIdx.y * 128 * DD;
    const __half* B = g_Ut + (size_t)blockIdx.x * 128 * DD;

    float acc[2][8][4];
    gemm_core(sb, A, B, acc);

    const int lane = threadIdx.x & 31;
    const int warp = threadIdx.x >> 5;
    const int wm = warp >> 1, wn = warp & 1;
    const int gid = lane >> 2, tig = lane & 3;

    #pragma unroll
    for (int mt = 0; mt < 2; mt++) {
        #pragma unroll
        for (int h = 0; h < 2; h++) {
            const int row = blockIdx.y * 128 + wm * 32 + mt * 16 + gid + h * 8;
            #pragma unroll
            for (int n8 = 0; n8 < 8; n8++) {
                const int col = blockIdx.x * 128 + wn * 64 + n8 * 8 + tig * 2;
                __half2 v = __floats2half2_rn(acc[mt][n8][h * 2], acc[mt][n8][h * 2 + 1]);
                *(unsigned*)(g_DUh + (size_t)row * DD + col) = *(unsigned*)&v;
            }
        }
    }
}

// ---------------------------------------------------------------------------
// GEMM B: out[b] = DU[b] @ H[b]^T + bx + by.  grid (4, 4, 64)
// ---------------------------------------------------------------------------
__global__ __launch_bounds__(256, 2)
void gemm_out_tc(float* __restrict__ out) {
    extern __shared__ char smem[];
    uint32_t sb = smem_u32(smem);
    const int b = blockIdx.z;

    const __half* A = g_DUh + ((size_t)b * NN + blockIdx.y * 128) * DD;
    const __half* B = g_Hh  + ((size_t)b * NN + blockIdx.x * 128) * DD;

    float acc[2][8][4];
    gemm_core(sb, A, B, acc);

    const int lane = threadIdx.x & 31;
    const int warp = threadIdx.x >> 5;
    const int wm = warp >> 1, wn = warp & 1;
    const int gid = lane >> 2, tig = lane & 3;

    #pragma unroll
    for (int mt = 0; mt < 2; mt++) {
        #pragma unroll
        for (int h = 0; h < 2; h++) {
            const int xg = blockIdx.y * 128 + wm * 32 + mt * 16 + gid + h * 8;
            const float bxv = g_bx[b * NN + xg];
            float* orow = out + ((size_t)b * NN + xg) * NN;
            #pragma unroll
            for (int n8 = 0; n8 < 8; n8++) {
                const int col = blockIdx.x * 128 + wn * 64 + n8 * 8 + tig * 2;
                float2 byv = *(const float2*)(g_by + b * NN + col);
                float2 v;
                v.x = acc[mt][n8][h * 2]     + bxv + byv.x;
                v.y = acc[mt][n8][h * 2 + 1] + bxv + byv.y;
                *(float2*)(orow + col) = v;
            }
        }
    }
}

// ---------------------------------------------------------------------------
// Launch
// ---------------------------------------------------------------------------
extern "C" void kernel_launch(void* const* d_in, const int* in_sizes, int n_in,
                              void* d_out, int out_size) {
    const float* D = (const float*)d_in[0];
    const float* H = (const float*)d_in[1];
    const float* U = (const float*)d_in[2];
    const float* W = (const float*)d_in[3];
    float* out = (float*)d_out;

    cudaFuncSetAttribute(gemm_du_tc,  cudaFuncAttributeMaxDynamicSharedMemorySize, SMEM_TOTAL);
    cudaFuncSetAttribute(gemm_out_tc, cudaFuncAttributeMaxDynamicSharedMemorySize, SMEM_TOTAL);

    prep_split_bias<<<(ROWS * 32) / 256, 256>>>(D, H, U, W);
    prep_u<<<dim3(32, 32), dim3(32, 8)>>>(U);

    gemm_du_tc<<<dim3(8, 256), 256, SMEM_TOTAL>>>();
    gemm_out_tc<<<dim3(4, 4, 64), 256, SMEM_TOTAL>>>(out);
}

// round 5
// speedup vs baseline: 6.9571x; 1.0130x over previous
#include <cuda_runtime.h>
#include <cuda_fp16.h>
#include <cstdint>

#define BB 64
#define NN 512
#define DD 1024
#define ROWS (BB * NN)   // 32768

// ---------------------------------------------------------------------------
// Device scratch (no runtime allocation allowed)
// ---------------------------------------------------------------------------
__device__ __half g_Dh [(size_t)ROWS * DD];
__device__ __half g_Hh [(size_t)ROWS * DD];
__device__ __half g_DUh[(size_t)ROWS * DD];
__device__ __half g_Ut [(size_t)DD * DD];    // U^T (N-major rows, K contiguous)
__device__ float g_bx[ROWS];
__device__ float g_by[ROWS];

// ---------------------------------------------------------------------------
// Helpers
// ---------------------------------------------------------------------------
__device__ __forceinline__ uint32_t smem_u32(const void* p) {
    uint32_t a;
    asm("{ .reg .u64 t; cvta.to.shared.u64 t, %1; cvt.u32.u64 %0, t; }" : "=r"(a) : "l"(p));
    return a;
}

__device__ __forceinline__ void cp_async16(uint32_t dst, const void* src) {
    asm volatile("cp.async.cg.shared.global [%0], [%1], 16;" :: "r"(dst), "l"(src));
}

#define CP_COMMIT() asm volatile("cp.async.commit_group;")

// Swizzled smem address: off = row*128 + col16*16, XOR bits[6:4] with row&7
__device__ __forceinline__ uint32_t sw_addr(uint32_t base, int row, int col16) {
    uint32_t off = (uint32_t)(row * 128 + col16 * 16);
    return base + (off ^ (((uint32_t)row & 7u) << 4));
}

#define LDSM4(r0, r1, r2, r3, addr) \
    asm volatile("ldmatrix.sync.aligned.m8n8.x4.shared.b16 {%0,%1,%2,%3}, [%4];" \
                 : "=r"(r0), "=r"(r1), "=r"(r2), "=r"(r3) : "r"(addr))

#define MMA16816(c, a0, a1, a2, a3, b0, b1) \
    asm volatile("mma.sync.aligned.m16n8k16.row.col.f32.f16.f16.f32 " \
                 "{%0,%1,%2,%3}, {%4,%5,%6,%7}, {%8,%9}, {%0,%1,%2,%3};" \
                 : "+f"((c)[0]), "+f"((c)[1]), "+f"((c)[2]), "+f"((c)[3]) \
                 : "r"(a0), "r"(a1), "r"(a2), "r"(a3), "r"(b0), "r"(b1))

// ---------------------------------------------------------------------------
// Prep: D,H -> fp16 + bias reductions (fused, one warp per row)
// ---------------------------------------------------------------------------
__global__ __launch_bounds__(256)
void prep_split_bias(const float* __restrict__ D, const float* __restrict__ H,
                     const float* __restrict__ U, const float* __restrict__ W) {
    __shared__ float sU[DD], sWh[DD], sWd[DD];
    for (int i = threadIdx.x; i < DD; i += blockDim.x) {
        sU[i]  = U[i * 1025 + 1024];
        sWh[i] = W[i];
        sWd[i] = W[1025 + i];
    }
    __syncthreads();

    int row  = (blockIdx.x * blockDim.x + threadIdx.x) >> 5;
    int lane = threadIdx.x & 31;
    if (row >= ROWS) return;

    const float4* drow = (const float4*)(D + (size_t)row * DD);
    const float4* hrow = (const float4*)(H + (size_t)row * DD);
    uint2* dh = (uint2*)(g_Dh + (size_t)row * DD);
    uint2* hh = (uint2*)(g_Hh + (size_t)row * DD);

    float s1 = 0.f, s2 = 0.f, s3 = 0.f;
    #pragma unroll
    for (int it = 0; it < 8; it++) {
        int i4 = it * 32 + lane;
        float4 d = drow[i4];
        float4 h = hrow[i4];
        int i = i4 * 4;
        s1 += d.x * sU[i]  + d.y * sU[i+1]  + d.z * sU[i+2]  + d.w * sU[i+3];
        s2 += h.x * sWh[i] + h.y * sWh[i+1] + h.z * sWh[i+2] + h.w * sWh[i+3];
        s3 += d.x * sWd[i] + d.y * sWd[i+1] + d.z * sWd[i+2] + d.w * sWd[i+3];

        __half2 d01 = __floats2half2_rn(d.x, d.y);
        __half2 d23 = __floats2half2_rn(d.z, d.w);
        __half2 h01 = __floats2half2_rn(h.x, h.y);
        __half2 h23 = __floats2half2_rn(h.z, h.w);
        dh[i4] = make_uint2(*(unsigned*)&d01, *(unsigned*)&d23);
        hh[i4] = make_uint2(*(unsigned*)&h01, *(unsigned*)&h23);
    }
    #pragma unroll
    for (int o = 16; o > 0; o >>= 1) {
        s1 += __shfl_xor_sync(0xFFFFFFFFu, s1, o);
        s2 += __shfl_xor_sync(0xFFFFFFFFu, s2, o);
        s3 += __shfl_xor_sync(0xFFFFFFFFu, s3, o);
    }
    if (lane == 0) {
        g_bx[row] = s1 + s2 + W[1024];
        g_by[row] = s3;
    }
}

// ---------------------------------------------------------------------------
// Prep: U^T -> fp16 (read U[k][n] stride 1025, write Ut[n][k])
// ---------------------------------------------------------------------------
__global__ void prep_u(const float* __restrict__ U) {
    __shared__ float t[32][33];
    int k0 = blockIdx.x * 32, n0 = blockIdx.y * 32;
    for (int i = threadIdx.y; i < 32; i += 8)
        t[i][threadIdx.x] = U[(size_t)(k0 + i) * 1025 + n0 + threadIdx.x];
    __syncthreads();
    for (int i = threadIdx.y; i < 32; i += 8) {
        float v = t[threadIdx.x][i];
        g_Ut[(size_t)(n0 + i) * DD + k0 + threadIdx.x] = __float2half_rn(v);
    }
}

// ---------------------------------------------------------------------------
// GEMM core: C(128x128 fp32 in regs) = A @ B^T, fp16 single pass.
// A, B: 128 rows x 1024 cols fp16, K-major. 3-stage cp.async, BK=64 (16 chunks).
// 128 threads, 4 warps (2x2), warp tile 64x64, mma.sync m16n8k16.
// ---------------------------------------------------------------------------
#define STAGE_BYTES 32768
#define SMEM_TOTAL  (3 * STAGE_BYTES)
#define NCHUNK 16

__device__ __forceinline__ void load_chunk(uint32_t tile,
        const __half* Asrc, const __half* Bsrc, int tid) {
    #pragma unroll
    for (int i = 0; i < 8; i++) {
        int idx = i * 128 + tid;
        int row = idx >> 3, g = idx & 7;
        uint32_t off = (uint32_t)(row * 128 + g * 16);
        uint32_t so = off ^ ((off >> 3) & 0x70);
        cp_async16(tile + so,         (const char*)Asrc + (size_t)row * 2048 + g * 16);
        cp_async16(tile + 16384 + so, (const char*)Bsrc + (size_t)row * 2048 + g * 16);
    }
}

__device__ __forceinline__ void gemm_core(uint32_t sb,
        const __half* A, const __half* B, float acc[4][8][4]) {
    const int tid  = threadIdx.x;
    const int lane = tid & 31;
    const int warp = tid >> 5;
    const int wm = warp >> 1;          // 0..1
    const int wn = warp & 1;           // 0..1

    #pragma unroll
    for (int mt = 0; mt < 4; mt++)
        #pragma unroll
        for (int n8 = 0; n8 < 8; n8++)
            #pragma unroll
            for (int q = 0; q < 4; q++) acc[mt][n8][q] = 0.f;

    // Prologue: 3 chunks
    #pragma unroll
    for (int c = 0; c < 3; c++) {
        load_chunk(sb + c * STAGE_BYTES, A + c * 64, B + c * 64, tid);
        CP_COMMIT();
    }

    const int a_row = lane & 15;
    const int a_kc  = lane >> 4;
    const int b_row = (lane & 7) + ((lane >> 4) & 1) * 8;
    const int b_kc  = (lane >> 3) & 1;

    #pragma unroll 1
    for (int c = 0; c < NCHUNK; c++) {
        const int s = c % 3;
        const uint32_t tile = sb + s * STAGE_BYTES;

        if (c < NCHUNK - 2)       asm volatile("cp.async.wait_group 2;");
        else if (c == NCHUNK - 2) asm volatile("cp.async.wait_group 1;");
        else                      asm volatile("cp.async.wait_group 0;");
        __syncthreads();

        #pragma unroll
        for (int ks = 0; ks < 4; ks++) {
            uint32_t a[4][4], b[4][4];
            #pragma unroll
            for (int mt = 0; mt < 4; mt++) {
                uint32_t ad = sw_addr(tile, wm * 64 + mt * 16 + a_row, ks * 2 + a_kc);
                LDSM4(a[mt][0], a[mt][1], a[mt][2], a[mt][3], ad);
            }
            #pragma unroll
            for (int nt = 0; nt < 4; nt++) {
                uint32_t bd = sw_addr(tile + 16384, wn * 64 + nt * 16 + b_row, ks * 2 + b_kc);
                LDSM4(b[nt][0], b[nt][1], b[nt][2], b[nt][3], bd);
            }
            #pragma unroll
            for (int mt = 0; mt < 4; mt++)
                #pragma unroll
                for (int n8 = 0; n8 < 8; n8++) {
                    const int nt = n8 >> 1, h = (n8 & 1) * 2;
                    MMA16816(acc[mt][n8], a[mt][0], a[mt][1], a[mt][2], a[mt][3],
                             b[nt][h], b[nt][h + 1]);
                }
        }
        __syncthreads();

        if (c + 3 < NCHUNK) {
            load_chunk(tile, A + (c + 3) * 64, B + (c + 3) * 64, tid);
            CP_COMMIT();
        }
    }
}

// ---------------------------------------------------------------------------
// GEMM A: DU = D @ U^T' -> fp16.  grid (8, 256), block 128
// ---------------------------------------------------------------------------
__global__ __launch_bounds__(128, 2)
void gemm_du_tc() {
    extern __shared__ char smem[];
    uint32_t sb = smem_u32(smem);

    const __half* A = g_Dh + (size_t)blockIdx.y * 128 * DD;
    const __half* B = g_Ut + (size_t)blockIdx.x * 128 * DD;

    float acc[4][8][4];
    gemm_core(sb, A, B, acc);

    const int lane = threadIdx.x & 31;
    const int warp = threadIdx.x >> 5;
    const int wm = warp >> 1, wn = warp & 1;
    const int gid = lane >> 2, tig = lane & 3;

    #pragma unroll
    for (int mt = 0; mt < 4; mt++) {
        #pragma unroll
        for (int h = 0; h < 2; h++) {
            const int row = blockIdx.y * 128 + wm * 64 + mt * 16 + gid + h * 8;
            #pragma unroll
            for (int n8 = 0; n8 < 8; n8++) {
                const int col = blockIdx.x * 128 + wn * 64 + n8 * 8 + tig * 2;
                __half2 v = __floats2half2_rn(acc[mt][n8][h * 2], acc[mt][n8][h * 2 + 1]);
                *(unsigned*)(g_DUh + (size_t)row * DD + col) = *(unsigned*)&v;
            }
        }
    }
}

// ---------------------------------------------------------------------------
// GEMM B: out[b] = DU[b] @ H[b]^T + bx + by.  grid (4, 4, 64), block 128
// ---------------------------------------------------------------------------
__global__ __launch_bounds__(128, 2)
void gemm_out_tc(float* __restrict__ out) {
    extern __shared__ char smem[];
    uint32_t sb = smem_u32(smem);
    const int b = blockIdx.z;

    const __half* A = g_DUh + ((size_t)b * NN + blockIdx.y * 128) * DD;
    const __half* B = g_Hh  + ((size_t)b * NN + blockIdx.x * 128) * DD;

    float acc[4][8][4];
    gemm_core(sb, A, B, acc);

    const int lane = threadIdx.x & 31;
    const int warp = threadIdx.x >> 5;
    const int wm = warp >> 1, wn = warp & 1;
    const int gid = lane >> 2, tig = lane & 3;

    #pragma unroll
    for (int mt = 0; mt < 4; mt++) {
        #pragma unroll
        for (int h = 0; h < 2; h++) {
            const int xg = blockIdx.y * 128 + wm * 64 + mt * 16 + gid + h * 8;
            const float bxv = g_bx[b * NN + xg];
            float* orow = out + ((size_t)b * NN + xg) * NN;
            #pragma unroll
            for (int n8 = 0; n8 < 8; n8++) {
                const int col = blockIdx.x * 128 + wn * 64 + n8 * 8 + tig * 2;
                float2 byv = *(const float2*)(g_by + b * NN + col);
                float2 v;
                v.x = acc[mt][n8][h * 2]     + bxv + byv.x;
                v.y = acc[mt][n8][h * 2 + 1] + bxv + byv.y;
                *(float2*)(orow + col) = v;
            }
        }
    }
}

// ---------------------------------------------------------------------------
// Launch
// ---------------------------------------------------------------------------
extern "C" void kernel_launch(void* const* d_in, const int* in_sizes, int n_in,
                              void* d_out, int out_size) {
    const float* D = (const float*)d_in[0];
    const float* H = (const float*)d_in[1];
    const float* U = (const float*)d_in[2];
    const float* W = (const float*)d_in[3];
    float* out = (float*)d_out;

    cudaFuncSetAttribute(gemm_du_tc,  cudaFuncAttributeMaxDynamicSharedMemorySize, SMEM_TOTAL);
    cudaFuncSetAttribute(gemm_out_tc, cudaFuncAttributeMaxDynamicSharedMemorySize, SMEM_TOTAL);

    prep_split_bias<<<(ROWS * 32) / 256, 256>>>(D, H, U, W);
    prep_u<<<dim3(32, 32), dim3(32, 8)>>>(U);

    gemm_du_tc<<<dim3(8, 256), 128, SMEM_TOTAL>>>();
    gemm_out_tc<<<dim3(4, 4, 64), 128, SMEM_TOTAL>>>(out);
}